// round 4
// baseline (speedup 1.0000x reference)
#include <cuda_runtime.h>
#include <math.h>

// Problem constants
#define DD    1024
#define KCLS  5
#define NSUP  5      // support per class
#define NQRY  75     // total queries (K*Q)
#define NAUG  40
#define NROWS 100    // 25 support + 75 queries
#define NSEG  8      // per-class dim segments for wide kernels (8*128 = 1024)
// hyperbolic constants: c = 0.01, sqrt(c) = 0.1

// ---------------- device scratch (static, no runtime alloc) ----------------
__device__ double g_P[NROWS * DD];      // projected Poincare points
__device__ double g_X2[NROWS];          // ||x||^2 per point
__device__ double g_KFAC[NROWS];        // 2/(1 + c||x||^2)  (Klein factor)
__device__ double g_LAM[NROWS];         // Lorentz factor of Klein point
__device__ double g_PROTO[KCLS * DD];   // initial prototypes
__device__ double g_PX2[KCLS];
__device__ int    g_PRED[NQRY];
__device__ double g_NLL[NQRY];
// k_aug decomposition scratch
__device__ double g_MKD[KCLS * DD];     // masked Klein mean per dim (post /wsum)
__device__ double g_STD[KCLS * DD];     // per-dim std of masked Euclid pts
__device__ double g_MK2P[KCLS * NSEG];  // partial sums of mkd^2
__device__ double g_CA[KCLS * NAUG];    // per-aug-row coefficient on s_p
__device__ double g_CB[KCLS * NAUG];    // per-aug-row coefficient on noise
__device__ double g_WL2[KCLS * NAUG];   // per-aug-row Lorentz weight
__device__ double g_M2[KCLS * DD];      // unnormalized refined Klein mean
__device__ double g_MK2BP[KCLS * NSEG]; // partial sums of m2^2

// ---------------- helpers ----------------
__device__ __forceinline__ double blk_reduce(double v, double* sbuf, int nwarps) {
    #pragma unroll
    for (int o = 16; o > 0; o >>= 1) v += __shfl_down_sync(0xffffffffu, v, o);
    int w = threadIdx.x >> 5, l = threadIdx.x & 31;
    if (l == 0) sbuf[w] = v;
    __syncthreads();
    if (w == 0) {
        double r = (l < nwarps) ? sbuf[l] : 0.0;
        #pragma unroll
        for (int o = 16; o > 0; o >>= 1) r += __shfl_down_sync(0xffffffffu, r, o);
        if (l == 0) sbuf[0] = r;
    }
    __syncthreads();
    double r = sbuf[0];
    __syncthreads();   // allow sbuf reuse
    return r;
}

// Poincare distance given ||x||^2, ||y||^2, <x,y>  (c = 0.01)
__device__ __forceinline__ double hdist(double x2, double y2, double xy) {
    double a    = 1.0 - 0.02 * xy + 0.01 * y2;
    double b    = 1.0 - 0.01 * x2;
    double num2 = a * a * x2 + b * b * y2 - 2.0 * a * b * xy;
    double den  = fmax(1.0 - 0.02 * xy + 1e-4 * x2 * y2, 1e-5);
    double nrm  = sqrt(fmax(num2, 0.0)) / den;
    double z    = fmin(fmax(0.1 * nrm, -1.0 + 1e-5), 1.0 - 1e-5);
    return 20.0 * atanh(z);   // (2/sqrt(c)) * artanh(sqrt(c)*norm), TEMP=1
}

// ---------------- K1: expmap0 + project + Klein scalars for all 100 rows ----------------
__global__ void k_transform(const float* __restrict__ feat) {
    __shared__ double sbuf[8];
    int row = blockIdx.x, tid = threadIdx.x;
    const float* u = feat + (size_t)row * DD;
    double uv[4];
    double s2 = 0.0;
    #pragma unroll
    for (int i = 0; i < 4; i++) { uv[i] = (double)u[tid + i * 256]; s2 += uv[i] * uv[i]; }
    s2 = blk_reduce(s2, sbuf, 8);

    double nrmu = sqrt(s2);
    double un   = fmax(nrmu, 1e-5);
    double s1   = tanh(0.1 * un) / (0.1 * un);   // expmap0 scale
    double e0n  = s1 * nrmu;
    double nrm  = fmax(e0n, 1e-5);
    double s    = s1;
    if (nrm > 9.99) s = s1 * (9.99 / nrm);       // project: maxnorm = 0.999/sqrt(c)
    double x2 = s * s * s2;

    #pragma unroll
    for (int i = 0; i < 4; i++)
        g_P[(size_t)row * DD + tid + i * 256] = s * uv[i];

    if (tid == 0) {
        g_X2[row] = x2;
        double kf = 2.0 / (1.0 + 0.01 * x2);
        double k2 = kf * kf * x2;
        g_KFAC[row] = kf;
        g_LAM[row]  = 1.0 / sqrt(fmax(1.0 - 0.01 * k2, 1e-5));
    }
}

// ---------------- K2: initial prototypes (Poincare mean of 5 support pts) ----------------
__global__ void k_proto() {
    __shared__ double sco[NSUP];
    __shared__ double swsum;
    __shared__ double sbuf[8];
    int c = blockIdx.x, tid = threadIdx.x;
    if (tid < NSUP) sco[tid] = g_LAM[c * NSUP + tid] * g_KFAC[c * NSUP + tid];
    if (tid == 0) {
        double w = 0.0;
        for (int n = 0; n < NSUP; n++) w += g_LAM[c * NSUP + n];
        swsum = w;
    }
    __syncthreads();
    double wsum = swsum;

    double mk[4]; double part = 0.0;
    #pragma unroll
    for (int i = 0; i < 4; i++) {
        int d = tid + i * 256;
        double a = 0.0;
        #pragma unroll
        for (int n = 0; n < NSUP; n++) a += sco[n] * g_P[(size_t)(c * NSUP + n) * DD + d];
        mk[i] = a / wsum;
        part += mk[i] * mk[i];
    }
    double mk2 = blk_reduce(part, sbuf, 8);
    double den = 1.0 + sqrt(fmax(1.0 - 0.01 * mk2, 0.0));   // k2p
    #pragma unroll
    for (int i = 0; i < 4; i++)
        g_PROTO[(size_t)c * DD + tid + i * 256] = mk[i] / den;
    if (tid == 0) g_PX2[c] = mk2 / (den * den);
}

// ---------------- K3: dist matrix, argmax pred, per-query NLL ----------------
__global__ void k_dist1(const int* __restrict__ label) {
    __shared__ double sbuf[8];
    __shared__ double sdots[KCLS];
    int q = blockIdx.x, tid = threadIdx.x;
    int row = 25 + q;

    double p5[KCLS] = {0.0, 0.0, 0.0, 0.0, 0.0};
    #pragma unroll
    for (int i = 0; i < 4; i++) {
        int d = tid + i * 256;
        double xv = g_P[(size_t)row * DD + d];
        #pragma unroll
        for (int j = 0; j < KCLS; j++) p5[j] += xv * g_PROTO[(size_t)j * DD + d];
    }
    #pragma unroll
    for (int j = 0; j < KCLS; j++) {
        double r = blk_reduce(p5[j], sbuf, 8);
        if (tid == 0) sdots[j] = r;
    }
    __syncthreads();

    if (tid == 0) {
        double x2 = g_X2[row];
        double dist[KCLS];
        int best = 0; double bd = 1e300;
        #pragma unroll
        for (int j = 0; j < KCLS; j++) {
            dist[j] = hdist(x2, g_PX2[j], sdots[j]);
            if (dist[j] < bd) { bd = dist[j]; best = j; }
        }
        g_PRED[q] = best;
        // loss term: log_softmax(log_softmax(-dist)) == log_softmax(-dist)
        double m = -1e300;
        #pragma unroll
        for (int j = 0; j < KCLS; j++) m = fmax(m, -dist[j]);
        double se = 0.0;
        #pragma unroll
        for (int j = 0; j < KCLS; j++) se += exp(-dist[j] - m);
        double lse = m + log(se);
        int lbl = label[NQRY + q];      // label[1][q]
        g_NLL[q] = lse + dist[lbl];     // -( -dist[lbl] - lse )
    }
}

// ---------------- K4a: per-class per-dim masked Klein mean + Euclid std ----------------
// grid = KCLS * NSEG blocks, 512 threads = 4 point-groups x 128 dims.
// Branchless (mask folded into coefficients), point loop split 4x20 and unrolled -> high MLP.
__global__ void __launch_bounds__(512) k_stats(const float* __restrict__ feat) {
    __shared__ double me[80], coef[80], wl[80];
    __shared__ int    srow[80];
    __shared__ double s_ak[4][128], s_ae[4][128], s_ae2[4][128];
    __shared__ double s_m2[128];
    __shared__ double s_wsum, s_cnt;

    int c = blockIdx.x >> 3, s = blockIdx.x & 7;
    int tid  = threadIdx.x;
    int g    = tid >> 7;          // point-group 0..3
    int lane = tid & 127;         // dim within segment
    int d    = s * 128 + lane;

    if (tid < 80) {
        int row; double mm;
        if (tid < NSUP) { row = c * NSUP + tid; mm = 1.0; }
        else            { row = 25 + (tid - NSUP); mm = (g_PRED[tid - NSUP] == c) ? 1.0 : 0.0; }
        me[tid]   = mm;
        srow[tid] = row;
        double lm = g_LAM[row];
        wl[tid]   = mm * lm;
        coef[tid] = mm * lm * g_KFAC[row];
    }
    __syncthreads();
    if (tid == 0) {
        double w = 0.0, cn = 0.0;
        for (int p = 0; p < 80; p++) { w += wl[p]; cn += me[p]; }
        s_wsum = w; s_cnt = cn;
    }

    double ak = 0.0, ae = 0.0, ae2 = 0.0;
    #pragma unroll
    for (int pi = 0; pi < 20; pi++) {
        int p     = g * 20 + pi;
        int row   = srow[p];
        double mm = me[p];
        double Pv = g_P[(size_t)row * DD + d];
        double Ev = (double)feat[(size_t)row * DD + d];
        ak  += coef[p] * Pv;
        ae  += mm * Ev;
        ae2 += mm * Ev * Ev;
    }
    s_ak[g][lane] = ak; s_ae[g][lane] = ae; s_ae2[g][lane] = ae2;
    __syncthreads();

    if (g == 0) {
        double AK  = s_ak[0][lane]  + s_ak[1][lane]  + s_ak[2][lane]  + s_ak[3][lane];
        double AE  = s_ae[0][lane]  + s_ae[1][lane]  + s_ae[2][lane]  + s_ae[3][lane];
        double AE2 = s_ae2[0][lane] + s_ae2[1][lane] + s_ae2[2][lane] + s_ae2[3][lane];
        double wsum = s_wsum, cnt = s_cnt;
        double mkd = AK / wsum;
        g_MKD[(size_t)c * DD + d] = mkd;
        double var = fmax(AE2 - AE * AE / cnt, 0.0) / (cnt - 1.0);
        g_STD[(size_t)c * DD + d] = sqrt(var);
        s_m2[lane] = mkd * mkd;
    }
    __syncthreads();
    if (tid == 0) {
        double part = 0.0;
        for (int i = 0; i < 128; i++) part += s_m2[i];
        g_MK2P[c * NSEG + s] = part;
    }
}

// ---------------- K4b: per (class, aug-row): pt reductions + scalar chain ----------------
// grid = KCLS * NAUG blocks, 256 threads
__global__ void k_augrow(const float* __restrict__ noise) {
    __shared__ double sbuf[8];
    __shared__ double s_den, s_x2sp, s_ptfac;

    int c = blockIdx.x / NAUG, j = blockIdx.x % NAUG;
    int tid = threadIdx.x;

    if (tid == 0) {
        double mk2 = 0.0;
        for (int s = 0; s < NSEG; s++) mk2 += g_MK2P[c * NSEG + s];
        double den = 1.0 + sqrt(fmax(1.0 - 0.01 * mk2, 0.0));
        s_den   = den;
        s_x2sp  = mk2 / (den * den);
        s_ptfac = 1.0 - 0.01 * (mk2 / (den * den));
    }
    __syncthreads();
    double den = s_den, x2sp = s_x2sp, ptfac = s_ptfac;

    const float* nz = noise + ((size_t)(c * NAUG + j)) * DD;
    double a2 = 0.0, ad = 0.0;
    #pragma unroll
    for (int i = 0; i < 4; i++) {
        int dd = tid + i * 256;
        double stdv = g_STD[(size_t)c * DD + dd];
        double ptv  = ptfac * (double)nz[dd] * stdv;
        double spv  = g_MKD[(size_t)c * DD + dd] / den;
        a2 += ptv * ptv;
        ad += spv * ptv;
    }
    a2 = blk_reduce(a2, sbuf, 8);
    ad = blk_reduce(ad, sbuf, 8);

    if (tid == 0) {
        double lamx = 2.0 / fmax(1.0 - 0.01 * x2sp, 1e-5);
        double pt2 = a2, dxp = ad;
        double un  = fmax(sqrt(pt2), 1e-5);
        double t   = tanh(0.05 * lamx * un) / (0.1 * un);
        double y2  = t * t * pt2;
        double xy  = t * dxp;
        double A   = 1.0 + 0.02 * xy + 0.01 * y2;
        double B   = ptfac * t;
        double dn  = fmax(1.0 + 0.02 * xy + 1e-4 * x2sp * y2, 1e-5);
        double ex2 = (A * A * x2sp + B * B * pt2 + 2.0 * A * B * dxp) / (dn * dn);
        double kf  = 2.0 / (1.0 + 0.01 * ex2);
        double k2  = kf * kf * ex2;
        double lm  = 1.0 / sqrt(fmax(1.0 - 0.01 * k2, 1e-5));
        g_CA[c * NAUG + j]  = lm * kf * A / dn;
        g_CB[c * NAUG + j]  = lm * kf * B / dn;
        g_WL2[c * NAUG + j] = lm;
    }
}

// ---------------- K4c: refined prototype per dim (unnormalized Klein mean) ----------------
// grid = KCLS * NSEG blocks, 512 threads = 4 row-groups x 128 dims.
__global__ void __launch_bounds__(512) k_newproto(const float* __restrict__ noise) {
    __shared__ double scb[NAUG], sco[NSUP];
    __shared__ double s_accN[4][128];
    __shared__ double s_m2s[128];
    __shared__ double s_wsum2, s_SA, s_ptfac, s_den;

    int c = blockIdx.x >> 3, s = blockIdx.x & 7;
    int tid  = threadIdx.x;
    int g    = tid >> 7;
    int lane = tid & 127;
    int d    = s * 128 + lane;

    if (tid < NAUG) scb[tid] = g_CB[c * NAUG + tid];
    if (tid >= 64 && tid < 64 + NSUP) sco[tid - 64] = g_LAM[c * NSUP + tid - 64] * g_KFAC[c * NSUP + tid - 64];
    if (tid == 0) {
        double mk2 = 0.0;
        for (int t = 0; t < NSEG; t++) mk2 += g_MK2P[c * NSEG + t];
        double den = 1.0 + sqrt(fmax(1.0 - 0.01 * mk2, 0.0));
        double x2sp = mk2 / (den * den);
        s_den = den;
        s_ptfac = 1.0 - 0.01 * x2sp;
        double w2 = 0.0, sa = 0.0;
        for (int n = 0; n < NSUP; n++) w2 += g_LAM[c * NSUP + n];
        for (int j = 0; j < NAUG; j++) { w2 += g_WL2[c * NAUG + j]; sa += g_CA[c * NAUG + j]; }
        s_wsum2 = w2; s_SA = sa;
    }
    __syncthreads();

    // noise-row loop split 4x10, fully unrolled
    double accN = 0.0;
    #pragma unroll
    for (int ji = 0; ji < 10; ji++) {
        int j = g * 10 + ji;
        accN += scb[j] * (double)noise[((size_t)(c * NAUG + j)) * DD + d];
    }
    s_accN[g][lane] = accN;
    __syncthreads();

    if (g == 0) {
        double acc = 0.0;
        #pragma unroll
        for (int n = 0; n < NSUP; n++)
            acc += sco[n] * g_P[(size_t)(c * NSUP + n) * DD + d];
        double spd = g_MKD[(size_t)c * DD + d] / s_den;
        acc += s_SA * spd;
        double AN = s_accN[0][lane] + s_accN[1][lane] + s_accN[2][lane] + s_accN[3][lane];
        acc += AN * s_ptfac * g_STD[(size_t)c * DD + d];

        double m2 = acc / s_wsum2;
        g_M2[(size_t)c * DD + d] = m2;
        s_m2s[lane] = m2 * m2;
    }
    __syncthreads();
    if (tid == 0) {
        double part = 0.0;
        for (int i = 0; i < 128; i++) part += s_m2s[i];
        g_MK2BP[c * NSEG + s] = part;
    }
}

// ---------------- K5: dist_new -> softmax y_pred; block 75 reduces loss ----------------
__global__ void k_final(float* __restrict__ out) {
    __shared__ double sbuf[8];
    __shared__ double sdots[KCLS];
    __shared__ double sden2[KCLS], sy2[KCLS];
    int q = blockIdx.x, tid = threadIdx.x;

    if (q == NQRY) {
        if (tid == 0) {
            double ssum = 0.0;
            for (int i = 0; i < NQRY; i++) ssum += g_NLL[i];
            out[NQRY * KCLS] = (float)(ssum / (double)NQRY);
        }
        return;
    }

    // per-class k2p normalization scalars (deferred from K4c)
    if (tid < KCLS) {
        double mk2b = 0.0;
        for (int s = 0; s < NSEG; s++) mk2b += g_MK2BP[tid * NSEG + s];
        double den2 = 1.0 + sqrt(fmax(1.0 - 0.01 * mk2b, 0.0));
        sden2[tid] = den2;
        sy2[tid]   = mk2b / (den2 * den2);
    }

    int row = 25 + q;
    double p5[KCLS] = {0.0, 0.0, 0.0, 0.0, 0.0};
    #pragma unroll
    for (int i = 0; i < 4; i++) {
        int d = tid + i * 256;
        double xv = g_P[(size_t)row * DD + d];
        #pragma unroll
        for (int j = 0; j < KCLS; j++) p5[j] += xv * g_M2[(size_t)j * DD + d];
    }
    #pragma unroll
    for (int j = 0; j < KCLS; j++) {
        double r = blk_reduce(p5[j], sbuf, 8);
        if (tid == 0) sdots[j] = r;
    }
    __syncthreads();

    if (tid == 0) {
        double x2 = g_X2[row];
        double dist[KCLS];
        double m = -1e300;
        #pragma unroll
        for (int j = 0; j < KCLS; j++) {
            dist[j] = hdist(x2, sy2[j], sdots[j] / sden2[j]);
            m = fmax(m, -dist[j]);
        }
        double e[KCLS]; double se = 0.0;
        #pragma unroll
        for (int j = 0; j < KCLS; j++) { e[j] = exp(-dist[j] - m); se += e[j]; }
        #pragma unroll
        for (int j = 0; j < KCLS; j++) out[q * KCLS + j] = (float)(e[j] / se);
    }
}

// ---------------- launch ----------------
extern "C" void kernel_launch(void* const* d_in, const int* in_sizes, int n_in,
                              void* d_out, int out_size) {
    const float* feat  = (const float*)d_in[0];
    const int*   label = (const int*)  d_in[1];
    const float* noise = (const float*)d_in[2];
    float* out = (float*)d_out;

    k_transform<<<NROWS, 256>>>(feat);
    k_proto<<<KCLS, 256>>>();
    k_dist1<<<NQRY, 256>>>(label);
    k_stats<<<KCLS * NSEG, 512>>>(feat);
    k_augrow<<<KCLS * NAUG, 256>>>(noise);
    k_newproto<<<KCLS * NSEG, 512>>>(noise);
    k_final<<<NQRY + 1, 256>>>(out);
}

// round 5
// speedup vs baseline: 1.1830x; 1.1830x over previous
#include <cuda_runtime.h>
#include <math.h>

// Problem constants
#define DD    1024
#define KCLS  5
#define NSUP  5      // support per class
#define NQRY  75     // total queries (K*Q)
#define NAUG  40
#define NROWS 100    // 25 support + 75 queries
#define NSEG  8      // per-class dim segments for wide kernels (8*128 = 1024)
// hyperbolic constants: c = 0.01, sqrt(c) = 0.1

// ---------------- device scratch (static, no runtime alloc) ----------------
__device__ double g_P[NROWS * DD];      // projected Poincare points
__device__ double g_X2[NROWS];          // ||x||^2 per point
__device__ double g_KFAC[NROWS];        // 2/(1 + c||x||^2)  (Klein factor)
__device__ double g_LAM[NROWS];         // Lorentz factor of Klein point
__device__ double g_PROTO[KCLS * DD];   // initial prototypes
__device__ double g_PX2[KCLS];
__device__ int    g_PRED[NQRY];
__device__ double g_NLL[NQRY];
// k_aug decomposition scratch
__device__ double g_MKD[KCLS * DD];     // masked Klein mean per dim (post /wsum)
__device__ double g_STD[KCLS * DD];     // per-dim std of masked Euclid pts
__device__ double g_MK2P[KCLS * NSEG];  // partial sums of mkd^2
__device__ double g_CA[KCLS * NAUG];    // per-aug-row coefficient on s_p
__device__ double g_CB[KCLS * NAUG];    // per-aug-row coefficient on noise
__device__ double g_WL2[KCLS * NAUG];   // per-aug-row Lorentz weight
__device__ double g_M2[KCLS * DD];      // unnormalized refined Klein mean
__device__ double g_MK2BP[KCLS * NSEG]; // partial sums of m2^2

// ---------------- helpers ----------------
__device__ __forceinline__ double blk_reduce(double v, double* sbuf, int nwarps) {
    #pragma unroll
    for (int o = 16; o > 0; o >>= 1) v += __shfl_down_sync(0xffffffffu, v, o);
    int w = threadIdx.x >> 5, l = threadIdx.x & 31;
    if (l == 0) sbuf[w] = v;
    __syncthreads();
    if (w == 0) {
        double r = (l < nwarps) ? sbuf[l] : 0.0;
        #pragma unroll
        for (int o = 16; o > 0; o >>= 1) r += __shfl_down_sync(0xffffffffu, r, o);
        if (l == 0) sbuf[0] = r;
    }
    __syncthreads();
    double r = sbuf[0];
    __syncthreads();
    return r;
}

// Poincare distance given ||x||^2, ||y||^2, <x,y>  (c = 0.01)
__device__ __forceinline__ double hdist(double x2, double y2, double xy) {
    double a    = 1.0 - 0.02 * xy + 0.01 * y2;
    double b    = 1.0 - 0.01 * x2;
    double num2 = a * a * x2 + b * b * y2 - 2.0 * a * b * xy;
    double den  = fmax(1.0 - 0.02 * xy + 1e-4 * x2 * y2, 1e-5);
    double nrm  = sqrt(fmax(num2, 0.0)) / den;
    double z    = fmin(fmax(0.1 * nrm, -1.0 + 1e-5), 1.0 - 1e-5);
    return 20.0 * atanh(z);   // (2/sqrt(c)) * artanh(sqrt(c)*norm), TEMP=1
}

// ---------------- K1: expmap0 + project + Klein scalars for all 100 rows ----------------
__global__ void k_transform(const float* __restrict__ feat) {
    __shared__ double sbuf[8];
    int row = blockIdx.x, tid = threadIdx.x;
    const float* u = feat + (size_t)row * DD;
    double uv[4];
    double s2 = 0.0;
    #pragma unroll
    for (int i = 0; i < 4; i++) { uv[i] = (double)u[tid + i * 256]; s2 += uv[i] * uv[i]; }
    s2 = blk_reduce(s2, sbuf, 8);

    double nrmu = sqrt(s2);
    double un   = fmax(nrmu, 1e-5);
    double s1   = tanh(0.1 * un) / (0.1 * un);   // expmap0 scale
    double e0n  = s1 * nrmu;
    double nrm  = fmax(e0n, 1e-5);
    double s    = s1;
    if (nrm > 9.99) s = s1 * (9.99 / nrm);       // project: maxnorm = 0.999/sqrt(c)
    double x2 = s * s * s2;

    #pragma unroll
    for (int i = 0; i < 4; i++)
        g_P[(size_t)row * DD + tid + i * 256] = s * uv[i];

    if (tid == 0) {
        g_X2[row] = x2;
        double kf = 2.0 / (1.0 + 0.01 * x2);
        double k2 = kf * kf * x2;
        g_KFAC[row] = kf;
        g_LAM[row]  = 1.0 / sqrt(fmax(1.0 - 0.01 * k2, 1e-5));
    }
}

// ---------------- K2: initial prototypes (Poincare mean of 5 support pts) ----------------
__global__ void k_proto() {
    __shared__ double sco[NSUP];
    __shared__ double srw;
    __shared__ double sbuf[8];
    int c = blockIdx.x, tid = threadIdx.x;
    if (tid < NSUP) sco[tid] = g_LAM[c * NSUP + tid] * g_KFAC[c * NSUP + tid];
    if (tid == 0) {
        double w = 0.0;
        for (int n = 0; n < NSUP; n++) w += g_LAM[c * NSUP + n];
        srw = 1.0 / w;
    }
    __syncthreads();
    double rwsum = srw;

    double mk[4]; double part = 0.0;
    #pragma unroll
    for (int i = 0; i < 4; i++) {
        int d = tid + i * 256;
        double a = 0.0;
        #pragma unroll
        for (int n = 0; n < NSUP; n++) a += sco[n] * g_P[(size_t)(c * NSUP + n) * DD + d];
        mk[i] = a * rwsum;
        part += mk[i] * mk[i];
    }
    double mk2 = blk_reduce(part, sbuf, 8);
    double den = 1.0 + sqrt(fmax(1.0 - 0.01 * mk2, 0.0));   // k2p
    double rden = 1.0 / den;
    #pragma unroll
    for (int i = 0; i < 4; i++)
        g_PROTO[(size_t)c * DD + tid + i * 256] = mk[i] * rden;
    if (tid == 0) g_PX2[c] = mk2 / (den * den);
}

// ---------------- K3: dist matrix, argmax pred, per-query NLL ----------------
__global__ void k_dist1(const int* __restrict__ label) {
    __shared__ double sred[8 * KCLS];
    __shared__ double sdots[KCLS];
    int q = blockIdx.x, tid = threadIdx.x;
    int row = 25 + q;
    int w = tid >> 5, l = tid & 31;

    double p5[KCLS] = {0.0, 0.0, 0.0, 0.0, 0.0};
    #pragma unroll
    for (int i = 0; i < 4; i++) {
        int d = tid + i * 256;
        double xv = g_P[(size_t)row * DD + d];
        #pragma unroll
        for (int j = 0; j < KCLS; j++) p5[j] += xv * g_PROTO[(size_t)j * DD + d];
    }
    #pragma unroll
    for (int j = 0; j < KCLS; j++) {
        double v = p5[j];
        #pragma unroll
        for (int o = 16; o > 0; o >>= 1) v += __shfl_down_sync(0xffffffffu, v, o);
        if (l == 0) sred[w * KCLS + j] = v;
    }
    __syncthreads();
    if (tid < KCLS) {
        double r = 0.0;
        #pragma unroll
        for (int ww = 0; ww < 8; ww++) r += sred[ww * KCLS + tid];
        sdots[tid] = r;
    }
    __syncthreads();

    if (tid == 0) {
        double x2 = g_X2[row];
        double dist[KCLS];
        int best = 0; double bd = 1e300;
        #pragma unroll
        for (int j = 0; j < KCLS; j++) {
            dist[j] = hdist(x2, g_PX2[j], sdots[j]);
            if (dist[j] < bd) { bd = dist[j]; best = j; }
        }
        g_PRED[q] = best;
        double m = -1e300;
        #pragma unroll
        for (int j = 0; j < KCLS; j++) m = fmax(m, -dist[j]);
        double se = 0.0;
        #pragma unroll
        for (int j = 0; j < KCLS; j++) se += exp(-dist[j] - m);
        double lse = m + log(se);
        int lbl = label[NQRY + q];      // label[1][q]
        g_NLL[q] = lse + dist[lbl];     // -( -dist[lbl] - lse )
    }
}

// ---------------- K4a: per-class per-dim masked Klein mean + Euclid std ----------------
// grid = KCLS * NSEG blocks, 512 threads = 4 point-groups x 128 dims.
// Active rows COMPACTED in original order -> fp64 loop runs only over ~cnt points.
__global__ void __launch_bounds__(512) k_stats(const float* __restrict__ feat) {
    __shared__ double sme[80], slam[80];
    __shared__ double scoef[80];
    __shared__ int    srow[80];
    __shared__ double s_ak[4][128], s_ae[4][128], s_ae2[4][128];
    __shared__ double s_m2[128];
    __shared__ double s_rwsum, s_cnt;
    __shared__ int    s_m;

    int c = blockIdx.x >> 3, s = blockIdx.x & 7;
    int tid  = threadIdx.x;
    int g    = tid >> 7;          // point-group 0..3
    int lane = tid & 127;         // dim within segment
    int d    = s * 128 + lane;

    if (tid < 80) {
        int row; double mm;
        if (tid < NSUP) { row = c * NSUP + tid; mm = 1.0; }
        else            { row = 25 + (tid - NSUP); mm = (g_PRED[tid - NSUP] == c) ? 1.0 : 0.0; }
        sme[tid]   = mm;
        srow[tid]  = row;
        double lm  = g_LAM[row];
        slam[tid]  = lm;
        scoef[tid] = lm * g_KFAC[row];
    }
    __syncthreads();
    if (tid == 0) {
        // compact active rows (in-place, original order) + scalar sums
        double wsum = 0.0, cn = 0.0; int m = 0;
        for (int p = 0; p < 80; p++) {
            if (sme[p] != 0.0) {
                wsum += slam[p]; cn += 1.0;
                srow[m] = srow[p]; scoef[m] = scoef[p]; m++;
            }
        }
        s_rwsum = 1.0 / wsum; s_cnt = cn; s_m = m;
    }
    __syncthreads();
    int m = s_m;

    double ak = 0.0, ae = 0.0, ae2 = 0.0;
    #pragma unroll 4
    for (int ji = g; ji < m; ji += 4) {
        int row   = srow[ji];
        double Pv = g_P[(size_t)row * DD + d];
        double Ev = (double)feat[(size_t)row * DD + d];
        ak  = fma(scoef[ji], Pv, ak);
        ae  += Ev;
        ae2 = fma(Ev, Ev, ae2);
    }
    s_ak[g][lane] = ak; s_ae[g][lane] = ae; s_ae2[g][lane] = ae2;
    __syncthreads();

    if (g == 0) {
        double AK  = s_ak[0][lane]  + s_ak[1][lane]  + s_ak[2][lane]  + s_ak[3][lane];
        double AE  = s_ae[0][lane]  + s_ae[1][lane]  + s_ae[2][lane]  + s_ae[3][lane];
        double AE2 = s_ae2[0][lane] + s_ae2[1][lane] + s_ae2[2][lane] + s_ae2[3][lane];
        double cnt = s_cnt;
        double mkd = AK * s_rwsum;
        g_MKD[(size_t)c * DD + d] = mkd;
        double var = fmax(AE2 - AE * AE / cnt, 0.0) / (cnt - 1.0);
        g_STD[(size_t)c * DD + d] = sqrt(var);
        s_m2[lane] = mkd * mkd;
    }
    __syncthreads();
    if (tid == 0) {
        double part = 0.0;
        for (int i = 0; i < 128; i++) part += s_m2[i];
        g_MK2P[c * NSEG + s] = part;
    }
}

// ---------------- K4b: per (class, aug-row): pt reductions + scalar chain ----------------
// grid = KCLS * NAUG blocks, 256 threads. Scalars hoisted out of the per-dim loop:
//   a2 = ptfac^2 * sum (nz*std)^2 ;  ad = (ptfac/den) * sum mkd*(nz*std)
__global__ void k_augrow(const float* __restrict__ noise) {
    __shared__ double sred[8 * 2];
    __shared__ double s_rden, s_x2sp, s_ptfac;

    int c = blockIdx.x / NAUG, j = blockIdx.x % NAUG;
    int tid = threadIdx.x;
    int w = tid >> 5, l = tid & 31;

    if (tid == 0) {
        double mk2 = 0.0;
        for (int s = 0; s < NSEG; s++) mk2 += g_MK2P[c * NSEG + s];
        double den = 1.0 + sqrt(fmax(1.0 - 0.01 * mk2, 0.0));
        s_rden  = 1.0 / den;
        double x2sp = mk2 / (den * den);
        s_x2sp  = x2sp;
        s_ptfac = 1.0 - 0.01 * x2sp;
    }
    __syncthreads();
    double rden = s_rden, x2sp = s_x2sp, ptfac = s_ptfac;

    const float* nz = noise + ((size_t)(c * NAUG + j)) * DD;
    double a2 = 0.0, ad = 0.0;
    #pragma unroll
    for (int i = 0; i < 4; i++) {
        int dd = tid + i * 256;
        double wv = (double)nz[dd] * g_STD[(size_t)c * DD + dd];
        a2 = fma(wv, wv, a2);
        ad = fma(g_MKD[(size_t)c * DD + dd], wv, ad);
    }
    #pragma unroll
    for (int o = 16; o > 0; o >>= 1) {
        a2 += __shfl_down_sync(0xffffffffu, a2, o);
        ad += __shfl_down_sync(0xffffffffu, ad, o);
    }
    if (l == 0) { sred[w * 2] = a2; sred[w * 2 + 1] = ad; }
    __syncthreads();

    if (tid == 0) {
        double A2 = 0.0, AD = 0.0;
        #pragma unroll
        for (int ww = 0; ww < 8; ww++) { A2 += sred[ww * 2]; AD += sred[ww * 2 + 1]; }
        double pt2 = ptfac * ptfac * A2;
        double dxp = ptfac * rden * AD;

        double lamx = 2.0 / fmax(1.0 - 0.01 * x2sp, 1e-5);
        double un  = fmax(sqrt(pt2), 1e-5);
        double t   = tanh(0.05 * lamx * un) / (0.1 * un);
        double y2  = t * t * pt2;
        double xy  = t * dxp;
        double A   = 1.0 + 0.02 * xy + 0.01 * y2;
        double B   = ptfac * t;
        double dn  = fmax(1.0 + 0.02 * xy + 1e-4 * x2sp * y2, 1e-5);
        double ex2 = (A * A * x2sp + B * B * pt2 + 2.0 * A * B * dxp) / (dn * dn);
        double kf  = 2.0 / (1.0 + 0.01 * ex2);
        double k2  = kf * kf * ex2;
        double lm  = 1.0 / sqrt(fmax(1.0 - 0.01 * k2, 1e-5));
        g_CA[c * NAUG + j]  = lm * kf * A / dn;
        g_CB[c * NAUG + j]  = lm * kf * B / dn;
        g_WL2[c * NAUG + j] = lm;
    }
}

// ---------------- K4c: refined prototype per dim (unnormalized Klein mean) ----------------
// grid = KCLS * NSEG blocks, 512 threads = 4 row-groups x 128 dims.
__global__ void __launch_bounds__(512) k_newproto(const float* __restrict__ noise) {
    __shared__ double scb[NAUG], sco[NSUP];
    __shared__ double s_accN[4][128];
    __shared__ double s_m2s[128];
    __shared__ double s_rwsum2, s_SA, s_ptfac, s_rden;

    int c = blockIdx.x >> 3, s = blockIdx.x & 7;
    int tid  = threadIdx.x;
    int g    = tid >> 7;
    int lane = tid & 127;
    int d    = s * 128 + lane;

    if (tid < NAUG) scb[tid] = g_CB[c * NAUG + tid];
    if (tid >= 64 && tid < 64 + NSUP) sco[tid - 64] = g_LAM[c * NSUP + tid - 64] * g_KFAC[c * NSUP + tid - 64];
    if (tid == 0) {
        double mk2 = 0.0;
        for (int t = 0; t < NSEG; t++) mk2 += g_MK2P[c * NSEG + t];
        double den = 1.0 + sqrt(fmax(1.0 - 0.01 * mk2, 0.0));
        double x2sp = mk2 / (den * den);
        s_rden  = 1.0 / den;
        s_ptfac = 1.0 - 0.01 * x2sp;
        double w2 = 0.0, sa = 0.0;
        for (int n = 0; n < NSUP; n++) w2 += g_LAM[c * NSUP + n];
        for (int j = 0; j < NAUG; j++) { w2 += g_WL2[c * NAUG + j]; sa += g_CA[c * NAUG + j]; }
        s_rwsum2 = 1.0 / w2; s_SA = sa;
    }
    __syncthreads();

    // noise-row loop split 4x10, fully unrolled
    double accN = 0.0;
    #pragma unroll
    for (int ji = 0; ji < 10; ji++) {
        int j = g * 10 + ji;
        accN = fma(scb[j], (double)noise[((size_t)(c * NAUG + j)) * DD + d], accN);
    }
    s_accN[g][lane] = accN;
    __syncthreads();

    if (g == 0) {
        double acc = 0.0;
        #pragma unroll
        for (int n = 0; n < NSUP; n++)
            acc = fma(sco[n], g_P[(size_t)(c * NSUP + n) * DD + d], acc);
        double spd = g_MKD[(size_t)c * DD + d] * s_rden;
        acc += s_SA * spd;
        double AN = s_accN[0][lane] + s_accN[1][lane] + s_accN[2][lane] + s_accN[3][lane];
        acc += AN * s_ptfac * g_STD[(size_t)c * DD + d];

        double m2 = acc * s_rwsum2;
        g_M2[(size_t)c * DD + d] = m2;
        s_m2s[lane] = m2 * m2;
    }
    __syncthreads();
    if (tid == 0) {
        double part = 0.0;
        for (int i = 0; i < 128; i++) part += s_m2s[i];
        g_MK2BP[c * NSEG + s] = part;
    }
}

// ---------------- K5: dist_new -> softmax y_pred; block 75 reduces loss ----------------
__global__ void k_final(float* __restrict__ out) {
    __shared__ double sred[8 * KCLS];
    __shared__ double sdots[KCLS];
    __shared__ double sden2[KCLS], sy2[KCLS];
    int q = blockIdx.x, tid = threadIdx.x;
    int w = tid >> 5, l = tid & 31;

    if (q == NQRY) {
        if (tid == 0) {
            double ssum = 0.0;
            for (int i = 0; i < NQRY; i++) ssum += g_NLL[i];
            out[NQRY * KCLS] = (float)(ssum / (double)NQRY);
        }
        return;
    }

    // per-class k2p normalization scalars (deferred from K4c)
    if (tid < KCLS) {
        double mk2b = 0.0;
        for (int s = 0; s < NSEG; s++) mk2b += g_MK2BP[tid * NSEG + s];
        double den2 = 1.0 + sqrt(fmax(1.0 - 0.01 * mk2b, 0.0));
        sden2[tid] = den2;
        sy2[tid]   = mk2b / (den2 * den2);
    }

    int row = 25 + q;
    double p5[KCLS] = {0.0, 0.0, 0.0, 0.0, 0.0};
    #pragma unroll
    for (int i = 0; i < 4; i++) {
        int d = tid + i * 256;
        double xv = g_P[(size_t)row * DD + d];
        #pragma unroll
        for (int j = 0; j < KCLS; j++) p5[j] += xv * g_M2[(size_t)j * DD + d];
    }
    #pragma unroll
    for (int j = 0; j < KCLS; j++) {
        double v = p5[j];
        #pragma unroll
        for (int o = 16; o > 0; o >>= 1) v += __shfl_down_sync(0xffffffffu, v, o);
        if (l == 0) sred[w * KCLS + j] = v;
    }
    __syncthreads();
    if (tid < KCLS) {
        double r = 0.0;
        #pragma unroll
        for (int ww = 0; ww < 8; ww++) r += sred[ww * KCLS + tid];
        sdots[tid] = r;
    }
    __syncthreads();

    if (tid == 0) {
        double x2 = g_X2[row];
        double dist[KCLS];
        double m = -1e300;
        #pragma unroll
        for (int j = 0; j < KCLS; j++) {
            dist[j] = hdist(x2, sy2[j], sdots[j] / sden2[j]);
            m = fmax(m, -dist[j]);
        }
        double e[KCLS]; double se = 0.0;
        #pragma unroll
        for (int j = 0; j < KCLS; j++) { e[j] = exp(-dist[j] - m); se += e[j]; }
        #pragma unroll
        for (int j = 0; j < KCLS; j++) out[q * KCLS + j] = (float)(e[j] / se);
    }
}

// ---------------- launch ----------------
extern "C" void kernel_launch(void* const* d_in, const int* in_sizes, int n_in,
                              void* d_out, int out_size) {
    const float* feat  = (const float*)d_in[0];
    const int*   label = (const int*)  d_in[1];
    const float* noise = (const float*)d_in[2];
    float* out = (float*)d_out;

    k_transform<<<NROWS, 256>>>(feat);
    k_proto<<<KCLS, 256>>>();
    k_dist1<<<NQRY, 256>>>(label);
    k_stats<<<KCLS * NSEG, 512>>>(feat);
    k_augrow<<<KCLS * NAUG, 256>>>(noise);
    k_newproto<<<KCLS * NSEG, 512>>>(noise);
    k_final<<<NQRY + 1, 256>>>(out);
}